// round 11
// baseline (speedup 1.0000x reference)
#include <cuda_runtime.h>
#include <math_constants.h>

#define IN_DIM 128
#define OUT_DIM 64
#define MAX_N 50000
#define MAX_E 800000
#define ALPHA_LEAKY 0.2f
#define EPS_F 1e-10f

#define SCAN_CHUNK 1024

// ---- scratch (device globals; no allocation allowed) ----
__device__ float  g_h[(size_t)MAX_N * OUT_DIM];   // 12.8 MB
__device__ float  g_ssrc[MAX_N];
__device__ float  g_stgt[MAX_N];
__device__ float  g_ws[IN_DIM];                   // W^T a[:64]
__device__ float  g_wt[IN_DIM];                   // W^T a[64:]
__device__ int    g_deg[MAX_N];
__device__ int    g_rowptr[MAX_N + 1];
__device__ int    g_rank[MAX_E];                  // per-edge rank within its target
__device__ int    g_bsum[(MAX_N + SCAN_CHUNK - 1) / SCAN_CHUNK];
__device__ float2 g_pack[MAX_E];                  // (exp(leaky score), src-as-float-bits)

// ---------------------------------------------------------------------------
// wv: w_s[k] = sum_o W[o][k]*a[o];  w_t[k] = sum_o W[o][k]*a[64+o]
// ---------------------------------------------------------------------------
__global__ void wv_kernel(const float* __restrict__ Wg, const float* __restrict__ a) {
    int k = threadIdx.x;    // 0..127
    float ws = 0.f, wt = 0.f;
#pragma unroll 8
    for (int o = 0; o < OUT_DIM; o++) {
        float w = __ldg(Wg + o * IN_DIM + k);
        ws = fmaf(w, __ldg(a + o), ws);
        wt = fmaf(w, __ldg(a + OUT_DIM + o), wt);
    }
    g_ws[k] = ws;
    g_wt[k] = wt;
}

// ---------------------------------------------------------------------------
// score: s_src[n] = X[n].w_s ; s_tgt[n] = X[n].w_t  (warp per node, side stream)
// ---------------------------------------------------------------------------
__global__ void __launch_bounds__(256) score_kernel(const float* __restrict__ X, int N) {
    int gw   = (blockIdx.x * blockDim.x + threadIdx.x) >> 5;
    int lane = threadIdx.x & 31;
    if (gw >= N) return;
    float4 x4 = ((const float4*)(X + (size_t)gw * IN_DIM))[lane];
    float4 s4 = ((const float4*)g_ws)[lane];
    float4 t4 = ((const float4*)g_wt)[lane];
    float ss = x4.x*s4.x + x4.y*s4.y + x4.z*s4.z + x4.w*s4.w;
    float st = x4.x*t4.x + x4.y*t4.y + x4.z*t4.z + x4.w*t4.w;
#pragma unroll
    for (int off = 16; off > 0; off >>= 1) {
        ss += __shfl_xor_sync(0xffffffffu, ss, off);
        st += __shfl_xor_sync(0xffffffffu, st, off);
    }
    if (lane == 0) {
        g_ssrc[gw] = ss;
        g_stgt[gw] = st;
    }
}

// ---------------------------------------------------------------------------
// histogram of targets + per-edge rank (free from the atomic return value)
// ---------------------------------------------------------------------------
__global__ void hist_kernel(const int* __restrict__ ei, int E) {
    int i = blockIdx.x * blockDim.x + threadIdx.x;
    if (i >= E) return;
    int tgt = __ldg(ei + E + i);
    g_rank[i] = atomicAdd(&g_deg[tgt], 1);
}

// ---------------------------------------------------------------------------
// exclusive scan, 3 phases (chunk=1024)  [side stream]
// ---------------------------------------------------------------------------
__global__ void __launch_bounds__(SCAN_CHUNK) scan1_kernel(int n) {
    __shared__ int wsum[32];
    int t = threadIdx.x, b = blockIdx.x;
    int gi = b * SCAN_CHUNK + t;
    int lane = t & 31, w = t >> 5;
    int v = (gi < n) ? g_deg[gi] : 0;
    int x = v;
#pragma unroll
    for (int off = 1; off < 32; off <<= 1) {
        int y = __shfl_up_sync(0xffffffffu, x, off);
        if (lane >= off) x += y;
    }
    if (lane == 31) wsum[w] = x;
    __syncthreads();
    if (w == 0) {
        int s = wsum[lane];
#pragma unroll
        for (int off = 1; off < 32; off <<= 1) {
            int y = __shfl_up_sync(0xffffffffu, s, off);
            if (lane >= off) s += y;
        }
        wsum[lane] = s;
    }
    __syncthreads();
    int incl = x + ((w > 0) ? wsum[w - 1] : 0);
    if (gi < n) g_rowptr[gi] = incl - v;
    if (t == SCAN_CHUNK - 1) g_bsum[b] = incl;
}

__global__ void __launch_bounds__(SCAN_CHUNK) scan2_kernel(int nb) {
    __shared__ int wsum[32];
    int t = threadIdx.x;
    int lane = t & 31, w = t >> 5;
    int v = (t < nb) ? g_bsum[t] : 0;
    int x = v;
#pragma unroll
    for (int off = 1; off < 32; off <<= 1) {
        int y = __shfl_up_sync(0xffffffffu, x, off);
        if (lane >= off) x += y;
    }
    if (lane == 31) wsum[w] = x;
    __syncthreads();
    if (w == 0) {
        int s = wsum[lane];
#pragma unroll
        for (int off = 1; off < 32; off <<= 1) {
            int y = __shfl_up_sync(0xffffffffu, s, off);
            if (lane >= off) s += y;
        }
        wsum[lane] = s;
    }
    __syncthreads();
    int incl = x + ((w > 0) ? wsum[w - 1] : 0);
    if (t < nb) g_bsum[t] = incl - v;
}

__global__ void scan3_kernel(int n, int E) {
    int gi = blockIdx.x * blockDim.x + threadIdx.x;
    if (gi < n)
        g_rowptr[gi] += g_bsum[gi >> 10];
    if (gi == 0) g_rowptr[n] = E;
}

// ---------------------------------------------------------------------------
// GEMM: g_h[n][o] = sum_k X[n][k] * W[o][k]
// 64 nodes x 64 outs per block, 256 threads, 4x4 register tile per thread.
// ---------------------------------------------------------------------------
#define WT_PITCH (OUT_DIM + 4)   // 68
#define XS_PITCH (IN_DIM + 4)    // 132
#define GEMM_SMEM_BYTES ((IN_DIM * WT_PITCH + 64 * XS_PITCH) * (int)sizeof(float))

__global__ void __launch_bounds__(256) gemm_kernel(
    const float* __restrict__ X, const float* __restrict__ Wg, int N)
{
    extern __shared__ float sm[];
    float* Wt = sm;                              // [IN_DIM][WT_PITCH]
    float* Xs = sm + IN_DIM * WT_PITCH;          // [64][XS_PITCH]

    int t = threadIdx.x;

    for (int i = t; i < IN_DIM * OUT_DIM; i += 256) {
        int o = i >> 7;
        int k = i & 127;
        Wt[k * WT_PITCH + o] = Wg[i];
    }

    int n0 = blockIdx.x * 64;
    for (int i = t; i < 64 * 32; i += 256) {
        int n  = i >> 5;
        int kq = i & 31;
        int gn = n0 + n;
        float4 v = make_float4(0.f, 0.f, 0.f, 0.f);
        if (gn < N) v = ((const float4*)(X + (size_t)gn * IN_DIM))[kq];
        ((float4*)(Xs + n * XS_PITCH))[kq] = v;
    }
    __syncthreads();

    int oq = (t & 15);
    int nq = (t >> 4) * 4;

    float acc[4][4];
#pragma unroll
    for (int j = 0; j < 4; j++)
#pragma unroll
        for (int c = 0; c < 4; c++) acc[j][c] = 0.0f;

#pragma unroll 8
    for (int k = 0; k < IN_DIM; k++) {
        float4 w4 = ((const float4*)(Wt + k * WT_PITCH))[oq];
#pragma unroll
        for (int j = 0; j < 4; j++) {
            float x = Xs[(nq + j) * XS_PITCH + k];
            acc[j][0] = fmaf(x, w4.x, acc[j][0]);
            acc[j][1] = fmaf(x, w4.y, acc[j][1]);
            acc[j][2] = fmaf(x, w4.z, acc[j][2]);
            acc[j][3] = fmaf(x, w4.w, acc[j][3]);
        }
    }

#pragma unroll
    for (int j = 0; j < 4; j++) {
        int gn = n0 + nq + j;
        if (gn < N) {
            float4 v = make_float4(acc[j][0], acc[j][1], acc[j][2], acc[j][3]);
            ((float4*)(g_h + (size_t)gn * OUT_DIM))[oq] = v;
        }
    }
}

// ---------------------------------------------------------------------------
// CSR fill (atomic-free): pos = rowptr[tgt] + rank[i].
// Stores (exp(leaky(e)), src). Max-free softmax: |e| <~ 20 so exp() is safe
// in fp32, and exp(e)/sum(exp(e)) == max-subtracted form algebraically.
// ---------------------------------------------------------------------------
__global__ void fill_kernel(const int* __restrict__ ei, int E) {
    int i = blockIdx.x * blockDim.x + threadIdx.x;
    if (i >= E) return;
    int src = __ldg(ei + i);
    int tgt = __ldg(ei + E + i);
    float e = g_ssrc[src] + g_stgt[tgt];
    e = (e > 0.0f) ? e : (ALPHA_LEAKY * e);
    float ex = __expf(e);
    int pos = g_rowptr[tgt] + g_rank[i];
    g_pack[pos] = make_float2(ex, __int_as_float(src));
}

// ---------------------------------------------------------------------------
// aggregate: one warp per target, single pass, broadcast loop unrolled x4
// so four independent 256B h-gathers are in flight per step.
// ---------------------------------------------------------------------------
__global__ void __launch_bounds__(256) agg_kernel(float* __restrict__ out, int N) {
    int gw   = (blockIdx.x * blockDim.x + threadIdx.x) >> 5;
    int lane = threadIdx.x & 31;
    if (gw >= N) return;

    int beg = g_rowptr[gw];
    int end = g_rowptr[gw + 1];

    float  S   = 0.0f;
    float2 acc = make_float2(0.0f, 0.0f);

    for (int base = beg; base < end; base += 32) {
        int j = base + lane;
        float ex = 0.0f;
        int   src = 0;
        if (j < end) {
            float2 p = __ldg(&g_pack[j]);
            ex  = p.x;
            src = __float_as_int(p.y);
        }
        int cnt = min(32, end - base);
        int k = 0;
        for (; k + 4 <= cnt; k += 4) {
            float a0 = __shfl_sync(0xffffffffu, ex, k);
            float a1 = __shfl_sync(0xffffffffu, ex, k + 1);
            float a2 = __shfl_sync(0xffffffffu, ex, k + 2);
            float a3 = __shfl_sync(0xffffffffu, ex, k + 3);
            int   s0 = __shfl_sync(0xffffffffu, src, k);
            int   s1 = __shfl_sync(0xffffffffu, src, k + 1);
            int   s2 = __shfl_sync(0xffffffffu, src, k + 2);
            int   s3 = __shfl_sync(0xffffffffu, src, k + 3);
            float2 h0 = __ldg((const float2*)(g_h + (size_t)s0 * OUT_DIM) + lane);
            float2 h1 = __ldg((const float2*)(g_h + (size_t)s1 * OUT_DIM) + lane);
            float2 h2 = __ldg((const float2*)(g_h + (size_t)s2 * OUT_DIM) + lane);
            float2 h3 = __ldg((const float2*)(g_h + (size_t)s3 * OUT_DIM) + lane);
            S += (a0 + a1) + (a2 + a3);
            acc.x = fmaf(a0, h0.x, acc.x);  acc.y = fmaf(a0, h0.y, acc.y);
            acc.x = fmaf(a1, h1.x, acc.x);  acc.y = fmaf(a1, h1.y, acc.y);
            acc.x = fmaf(a2, h2.x, acc.x);  acc.y = fmaf(a2, h2.y, acc.y);
            acc.x = fmaf(a3, h3.x, acc.x);  acc.y = fmaf(a3, h3.y, acc.y);
        }
        for (; k < cnt; k++) {
            float a  = __shfl_sync(0xffffffffu, ex, k);
            int   sk = __shfl_sync(0xffffffffu, src, k);
            S += a;
            float2 hv = __ldg((const float2*)(g_h + (size_t)sk * OUT_DIM) + lane);
            acc.x = fmaf(a, hv.x, acc.x);
            acc.y = fmaf(a, hv.y, acc.y);
        }
    }

    float inv = 1.0f / (S + EPS_F);
    float2 o;
    o.x = acc.x * inv;
    o.y = acc.y * inv;
    o.x = (o.x > 0.0f) ? o.x : expm1f(o.x);
    o.y = (o.y > 0.0f) ? o.y : expm1f(o.y);
    ((float2*)(out + (size_t)gw * OUT_DIM))[lane] = o;
}

extern "C" void kernel_launch(void* const* d_in, const int* in_sizes, int n_in,
                              void* d_out, int out_size) {
    const float* X   = (const float*)d_in[0];
    const int*   EI  = (const int*)d_in[1];      // int32 edge_index [2, E]
    const float* Wg  = (const float*)d_in[2];
    const float* A   = (const float*)d_in[3];
    float*       out = (float*)d_out;

    int N = in_sizes[0] / IN_DIM;   // 50000
    int E = in_sizes[1] / 2;        // 800000
    int nb = (N + SCAN_CHUNK - 1) / SCAN_CHUNK;

    // one-time host-side resources (no device memory allocated)
    static cudaStream_t s2 = nullptr, s3 = nullptr;
    static cudaEvent_t  e0 = nullptr, eScore = nullptr, eFill = nullptr;
    static void* deg_ptr = nullptr;
    if (s2 == nullptr) {
        cudaStreamCreateWithFlags(&s2, cudaStreamNonBlocking);
        cudaStreamCreateWithFlags(&s3, cudaStreamNonBlocking);
        cudaEventCreateWithFlags(&e0, cudaEventDisableTiming);
        cudaEventCreateWithFlags(&eScore, cudaEventDisableTiming);
        cudaEventCreateWithFlags(&eFill, cudaEventDisableTiming);
        cudaGetSymbolAddress(&deg_ptr, g_deg);
        cudaFuncSetAttribute(gemm_kernel,
                             cudaFuncAttributeMaxDynamicSharedMemorySize,
                             GEMM_SMEM_BYTES);
    }

    // fork
    cudaEventRecord(e0, (cudaStream_t)0);
    cudaStreamWaitEvent(s2, e0, 0);
    cudaStreamWaitEvent(s3, e0, 0);

    // chain B (s3): scores directly from X (independent of GEMM)
    wv_kernel<<<1, IN_DIM, 0, s3>>>(Wg, A);
    score_kernel<<<(unsigned)(((size_t)N * 32 + 255) / 256), 256, 0, s3>>>(X, N);
    cudaEventRecord(eScore, s3);

    // chain A (s2): CSR build, then atomic-free fill (needs scores from B)
    cudaMemsetAsync(deg_ptr, 0, (size_t)N * sizeof(int), s2);
    hist_kernel<<<(E + 255) / 256, 256, 0, s2>>>(EI, E);
    scan1_kernel<<<nb, SCAN_CHUNK, 0, s2>>>(N);
    scan2_kernel<<<1, SCAN_CHUNK, 0, s2>>>(nb);
    scan3_kernel<<<(N + 255) / 256, 256, 0, s2>>>(N, E);
    cudaStreamWaitEvent(s2, eScore, 0);
    fill_kernel<<<(E + 255) / 256, 256, 0, s2>>>(EI, E);
    cudaEventRecord(eFill, s2);

    // main chain: GEMM concurrent with A and B
    gemm_kernel<<<(N + 63) / 64, 256, GEMM_SMEM_BYTES>>>(X, Wg, N);

    // join: agg needs h (main, in-order) + pack (side A)
    cudaStreamWaitEvent((cudaStream_t)0, eFill, 0);
    agg_kernel<<<(unsigned)(((size_t)N * 32 + 255) / 256), 256>>>(out, N);
}